// round 4
// baseline (speedup 1.0000x reference)
#include <cuda_runtime.h>

// y = x*2 + 5 - 3/(1+x), elementwise over 8192*8192 fp32 (64M elems).
// R4: back to V=4 (best DRAM%), 512-thread blocks, and write-through stores
// (__stwt) to avoid dirty-L2-line writeback churn on the streaming output.

constexpr int V = 4;        // float4 per thread
constexpr int T = 512;      // threads per block

__global__ __launch_bounds__(T)
void elementwise_f4x4_wt_kernel(const float4* __restrict__ in,
                                float4* __restrict__ out) {
    int base = blockIdx.x * (T * V) + threadIdx.x;

    float4 v[V];
#pragma unroll
    for (int k = 0; k < V; k++) {
        v[k] = __ldcs(&in[base + k * T]);   // front-batched streaming loads
    }

#pragma unroll
    for (int k = 0; k < V; k++) {
        float4 r;
        r.x = fmaf(v[k].x, 2.0f, 5.0f) - 3.0f / (1.0f + v[k].x);
        r.y = fmaf(v[k].y, 2.0f, 5.0f) - 3.0f / (1.0f + v[k].y);
        r.z = fmaf(v[k].z, 2.0f, 5.0f) - 3.0f / (1.0f + v[k].z);
        r.w = fmaf(v[k].w, 2.0f, 5.0f) - 3.0f / (1.0f + v[k].w);
        __stwt(&out[base + k * T], r);       // write-through store
    }
}

extern "C" void kernel_launch(void* const* d_in, const int* in_sizes, int n_in,
                              void* d_out, int out_size) {
    const float* x = (const float*)d_in[0];
    float* y = (float*)d_out;
    int n = in_sizes[0];          // 67108864 = 8192*8192
    int n4 = n >> 2;              // 16777216 float4

    // Exact division: 16777216 / (512*4) = 8192 blocks, no tail.
    int blocks = n4 / (T * V);
    elementwise_f4x4_wt_kernel<<<blocks, T>>>(
        (const float4*)x, (float4*)y);
}

// round 5
// speedup vs baseline: 1.0117x; 1.0117x over previous
#include <cuda_runtime.h>
#include <cstdint>

// y = x*2 + 5 - 3/(1+x), elementwise over 8192*8192 fp32 (64M elems).
// R5: 256-bit vector loads/stores (sm_100+ ld/st.global.v8.b32) with streaming
// hints, MLP=4 v8-chunks per thread, fast reciprocal for the division.

constexpr int T  = 256;   // threads per block
constexpr int VL = 4;     // v8 chunks per thread (32 floats/thread)

__device__ __forceinline__ void ldg_v8_cs(const float* p, float* r) {
    asm volatile(
        "ld.global.cs.v8.b32 {%0,%1,%2,%3,%4,%5,%6,%7}, [%8];"
        : "=f"(r[0]), "=f"(r[1]), "=f"(r[2]), "=f"(r[3]),
          "=f"(r[4]), "=f"(r[5]), "=f"(r[6]), "=f"(r[7])
        : "l"(p));
}

__device__ __forceinline__ void stg_v8_cs(float* p, const float* r) {
    asm volatile(
        "st.global.cs.v8.b32 [%0], {%1,%2,%3,%4,%5,%6,%7,%8};"
        :: "l"(p),
           "f"(r[0]), "f"(r[1]), "f"(r[2]), "f"(r[3]),
           "f"(r[4]), "f"(r[5]), "f"(r[6]), "f"(r[7])
        : "memory");
}

__global__ __launch_bounds__(T)
void elementwise_v8_kernel(const float* __restrict__ in,
                           float* __restrict__ out) {
    // Block covers T*VL*8 = 8192 consecutive floats.
    // Thread t handles 32B chunk at t*8 + k*(T*8), k in [0,VL).
    int base = blockIdx.x * (T * VL * 8) + threadIdx.x * 8;

    float v[VL][8];
#pragma unroll
    for (int k = 0; k < VL; k++) {
        ldg_v8_cs(in + base + k * (T * 8), v[k]);   // front-batched LDG.E.256
    }

#pragma unroll
    for (int k = 0; k < VL; k++) {
        float r[8];
#pragma unroll
        for (int j = 0; j < 8; j++) {
            r[j] = fmaf(v[k][j], 2.0f, 5.0f) - __fdividef(3.0f, 1.0f + v[k][j]);
        }
        stg_v8_cs(out + base + k * (T * 8), r);     // STG.E.256
    }
}

extern "C" void kernel_launch(void* const* d_in, const int* in_sizes, int n_in,
                              void* d_out, int out_size) {
    const float* x = (const float*)d_in[0];
    float* y = (float*)d_out;
    int n = in_sizes[0];                  // 67108864 = 8192*8192

    // Exact division: 67108864 / (256*4*8) = 8192 blocks, no tail.
    int blocks = n / (T * VL * 8);
    elementwise_v8_kernel<<<blocks, T>>>(x, y);
}

// round 6
// speedup vs baseline: 1.0164x; 1.0047x over previous
#include <cuda_runtime.h>

// y = x*2 + 5 - 3/(1+x), elementwise over 8192*8192 fp32 (64M elems).
// FINAL: R2 shape (best measured: 6.50 TB/s, DRAM 82.1%) + fast reciprocal.
//   - 4x float4 per thread, front-batched (MLP=4), 256-thread blocks
//   - streaming cache hints (ld/st.global.cs) on the pass-through data
//   - __fdividef: MUFU.RCP+MUL instead of refined divide (rel_err ~3e-8)
// Pinned at the mixed read+write HBM3e wall (~6.5 TB/s on this part).

constexpr int V = 4;    // float4 per thread
constexpr int T = 256;  // threads per block

__global__ __launch_bounds__(T)
void elementwise_final_kernel(const float4* __restrict__ in,
                              float4* __restrict__ out) {
    int base = blockIdx.x * (T * V) + threadIdx.x;

    float4 v[V];
#pragma unroll
    for (int k = 0; k < V; k++) {
        v[k] = __ldcs(&in[base + k * T]);   // 4 independent LDG.E.128, front-batched
    }

#pragma unroll
    for (int k = 0; k < V; k++) {
        float4 r;
        r.x = fmaf(v[k].x, 2.0f, 5.0f) - __fdividef(3.0f, 1.0f + v[k].x);
        r.y = fmaf(v[k].y, 2.0f, 5.0f) - __fdividef(3.0f, 1.0f + v[k].y);
        r.z = fmaf(v[k].z, 2.0f, 5.0f) - __fdividef(3.0f, 1.0f + v[k].z);
        r.w = fmaf(v[k].w, 2.0f, 5.0f) - __fdividef(3.0f, 1.0f + v[k].w);
        __stcs(&out[base + k * T], r);
    }
}

extern "C" void kernel_launch(void* const* d_in, const int* in_sizes, int n_in,
                              void* d_out, int out_size) {
    const float* x = (const float*)d_in[0];
    float* y = (float*)d_out;
    int n = in_sizes[0];          // 67108864 = 8192*8192
    int n4 = n >> 2;              // 16777216 float4

    // Exact tiling: 16777216 / (256*4) = 16384 blocks, no tail.
    int blocks = n4 / (T * V);
    elementwise_final_kernel<<<blocks, T>>>(
        (const float4*)x, (float4*)y);
}